// round 14
// baseline (speedup 1.0000x reference)
#include <cuda_runtime.h>
#include <cuda_bf16.h>
#include <cstdint>

typedef unsigned long long u64;

// ---------------- config ----------------
constexpr int TPB = 288;        // 9 warps: warp w owns 2 m-tiles for all 256 edges
constexpr int EPB = 256;

// smem byte offsets
constexpr int OFF_HHI = 0;               // h hi: 256 edges x 35 u32 = 35840B
constexpr int OFF_HLO = 35840;           // h lo: 35840B
constexpr int OFF_TP  = 71680;           // tp: 256 x 16 f32 = 16384B
constexpr int OFF_BUF = 88064;           // 9 warps x 2 bufs x 288 f32 = 20736B
constexpr int OFF_BES = 108800;          // bessel W0 rows: 512 f32 = 2048B
constexpr int OFF_CST = 110848;          // 16 f32
constexpr int SMEM_BYTES = 110912;       // x2 CTAs = 221,824B

constexpr int BSTR = 36;                 // D-buf row stride in floats (16B aligned)

// m-tile pairing per warp (balance epilogue output volume):
// mtiles: 0-7 latent(16 out) 8-11 f0(8) 12-15 f1(24) 16-17 f2(80)
__device__ const int g_mt0[9] = {16, 17, 12, 13, 14, 15,  8,  9, 6};
__device__ const int g_mt1[9] = {10, 11,  0,  1,  2,  3,  4,  5, 7};

// ---------------- device scratch ----------------
__device__ __align__(16) uint32_t g_afrag_hi[9216];  // 18 mt x 4 kt x 32 lanes x 4 regs
__device__ __align__(16) uint32_t g_afrag_lo[9216];

__device__ __forceinline__ float silu_f(float v) { return v / (1.0f + __expf(-v)); }

// ---------------- fused prep: A fragments (hi/lo bf16), W1@We inline ----------------
__global__ void afrag_kernel(const float* __restrict__ W1, const float* __restrict__ We) {
    constexpr float S1 = 1.6789f * 0.125f;
    constexpr float S2 = 0.08838834764831845f;
    int idx = blockIdx.x * blockDim.x + threadIdx.x;
    if (idx >= 9216) return;
    int ri = idx & 3, t = (idx >> 2) & 31, kt = (idx >> 7) & 3, mt = idx >> 9;
    int m  = mt * 16 + (t >> 2) + (ri & 1) * 8;
    int k0 = kt * 16 + (t & 3) * 2 + (ri >> 1) * 8;

    float v0, v1;
    if (m < 128) {
        v0 = W1[k0 * 128 + m] * S1;
        v1 = W1[(k0 + 1) * 128 + m] * S1;
    } else {
        int cm;
        if (m < 192)      { int p = (m - 128) >> 1, s = (m - 128) & 1; cm = p + 32 * s; }
        else if (m < 256) { int p = (m - 192) >> 1, s = (m - 192) & 1; cm = 64 + p + 32 * s; }
        else                cm = 128 + (m - 256);
        float a0 = 0.0f, a1 = 0.0f;
        const float* w1a = W1 + k0 * 128;
        const float* w1b = W1 + (k0 + 1) * 128;
#pragma unroll 8
        for (int j = 0; j < 128; j++) {
            const float we = __ldg(We + j * 160 + cm);
            a0 = fmaf(__ldg(w1a + j), we, a0);
            a1 = fmaf(__ldg(w1b + j), we, a1);
        }
        v0 = a0 * (S1 * S2);
        v1 = a1 * (S1 * S2);
    }

    __nv_bfloat16 h0 = __float2bfloat16(v0);
    __nv_bfloat16 h1 = __float2bfloat16(v1);
    __nv_bfloat16 l0 = __float2bfloat16(v0 - __bfloat162float(h0));
    __nv_bfloat16 l1 = __float2bfloat16(v1 - __bfloat162float(h1));
    g_afrag_hi[idx] = (uint32_t)__bfloat16_as_ushort(h0) | ((uint32_t)__bfloat16_as_ushort(h1) << 16);
    g_afrag_lo[idx] = (uint32_t)__bfloat16_as_ushort(l0) | ((uint32_t)__bfloat16_as_ushort(l1) << 16);
}

// ---------------- mma helper ----------------
__device__ __forceinline__ void mma16816(float* d, const uint4& a, uint32_t b0, uint32_t b1) {
    asm volatile(
        "mma.sync.aligned.m16n8k16.row.col.f32.bf16.bf16.f32 "
        "{%0,%1,%2,%3}, {%4,%5,%6,%7}, {%8,%9}, {%0,%1,%2,%3};"
        : "+f"(d[0]), "+f"(d[1]), "+f"(d[2]), "+f"(d[3])
        : "r"(a.x), "r"(a.y), "r"(a.z), "r"(a.w), "r"(b0), "r"(b1));
}

// ---------------- per-mtile epilogue (mt is warp-uniform) ----------------
__device__ __forceinline__ void epi_mtile(int mt, const float* __restrict__ row,
                                          const float* __restrict__ tp,
                                          float* __restrict__ lat_e,
                                          float* __restrict__ feat_e, int t3) {
    if (mt < 8) {
        const float cl = tp[0];
        float4 v = *reinterpret_cast<const float4*>(row + 4 * t3);
        v.x *= cl; v.y *= cl; v.z *= cl; v.w *= cl;
        *reinterpret_cast<float4*>(lat_e + mt * 16 + 4 * t3) = v;
    } else if (mt < 12) {
        const float ta = tp[1], tb = tp[2];
        float2 v;
        v.x = row[4 * t3]     * ta + row[4 * t3 + 1] * tb;
        v.y = row[4 * t3 + 2] * ta + row[4 * t3 + 3] * tb;
        *reinterpret_cast<float2*>(feat_e + (mt - 8) * 8 + 2 * t3) = v;
    } else if (mt < 16) {
        float* dst = feat_e + 32 + (mt - 12) * 24 + 6 * t3;
        const float a0 = row[4 * t3], b0 = row[4 * t3 + 1];
        const float a1 = row[4 * t3 + 2], b1 = row[4 * t3 + 3];
        float2 v0, v1, v2;
        v0.x = a0 * tp[3] + b0 * tp[6];
        v0.y = a0 * tp[4] + b0 * tp[7];
        v1.x = a0 * tp[5] + b0 * tp[8];
        v1.y = a1 * tp[3] + b1 * tp[6];
        v2.x = a1 * tp[4] + b1 * tp[7];
        v2.y = a1 * tp[5] + b1 * tp[8];
        reinterpret_cast<float2*>(dst)[0] = v0;
        reinterpret_cast<float2*>(dst)[1] = v1;
        reinterpret_cast<float2*>(dst)[2] = v2;
    } else {
        float* dst = feat_e + 128 + (mt - 16) * 80 + 20 * t3;
        float v[20];
#pragma unroll
        for (int j = 0; j < 4; j++) {
            const float a = row[4 * t3 + j];
#pragma unroll
            for (int i = 0; i < 5; i++) v[5 * j + i] = a * tp[9 + i];
        }
#pragma unroll
        for (int t = 0; t < 5; t++)
            reinterpret_cast<float4*>(dst)[t] =
                make_float4(v[4 * t], v[4 * t + 1], v[4 * t + 2], v[4 * t + 3]);
    }
}

// ---------------- main kernel ----------------
__global__ void __launch_bounds__(TPB, 2)
e3_mma_kernel(const int*   __restrict__ eidx,
              const float* __restrict__ esh,
              const float* __restrict__ elen,
              const float* __restrict__ onehot,
              const float* __restrict__ bw,
              const float* __restrict__ tpw,
              const float* __restrict__ W0,
              float*       __restrict__ out,
              int E)
{
    extern __shared__ __align__(16) char smc[];
    const int tid  = threadIdx.x;
    const int warp = tid >> 5;
    const int lane = tid & 31;
    const int t3   = lane & 3;
    const int g    = lane >> 2;

    // ---- small cooperative loads ----
    if (tid < 256) {
        float* bes = reinterpret_cast<float*>(smc + OFF_BES);
        bes[tid]       = W0[32 * 64 + tid];
        bes[tid + 256] = W0[32 * 64 + 256 + tid];
        float* cst = reinterpret_cast<float*>(smc + OFF_CST);
        if (tid < 8)       cst[tid] = bw[tid];
        else if (tid < 15) cst[tid] = tpw[tid - 8];
    }
    __syncthreads();

    const float* bes = reinterpret_cast<const float*>(smc + OFF_BES);
    const float* cst = reinterpret_cast<const float*>(smc + OFF_CST);
    float* tparr = reinterpret_cast<float*>(smc + OFF_TP);

    float* __restrict__ lat_out  = out;
    float* __restrict__ feat_out = out + (size_t)E * 128;
    float* __restrict__ cut_out  = out + (size_t)E * 416;

    // ================= stage 1: first 256 threads, one edge each =================
    if (tid < 256) {
        const int e = blockIdx.x * EPB + tid;
        const int   src = eidx[e];
        const int   dst = eidx[E + e];
        const float r   = elen[e];
        const float4 shv = reinterpret_cast<const float4*>(esh)[e];

        int ts = 0, td = 0;
        {
            const float4* rs = reinterpret_cast<const float4*>(onehot + (size_t)src * 16);
            const float4* rd = reinterpret_cast<const float4*>(onehot + (size_t)dst * 16);
#pragma unroll
            for (int q4 = 0; q4 < 4; q4++) {
                float4 a = __ldg(rs + q4); float4 b = __ldg(rd + q4);
                int base = q4 * 4;
                if (a.x > 0.5f) ts = base;     if (a.y > 0.5f) ts = base + 1;
                if (a.z > 0.5f) ts = base + 2; if (a.w > 0.5f) ts = base + 3;
                if (b.x > 0.5f) td = base;     if (b.y > 0.5f) td = base + 1;
                if (b.z > 0.5f) td = base + 2; if (b.w > 0.5f) td = base + 3;
            }
        }

        const float x    = r * 0.2f;
        const float invr = 1.0f / r;
        float eb[8];
#pragma unroll
        for (int j = 0; j < 8; j++)
            eb[j] = 0.4f * __sinf(cst[j] * x) * invr;

        const float x3 = x * x * x, x6 = x3 * x3, x7 = x6 * x, x8 = x7 * x;
        const float poly = 1.0f - 28.0f * x6 + 48.0f * x7 - 21.0f * x8;
        const float cutv = (x < 1.0f) ? poly : 0.0f;
        const float cl   = (cutv > 0.0f) ? cutv : 0.0f;
        cut_out[e] = cutv;

        // h = silu(S0*(W0[ts] + W0[16+td] + eb @ bessel_rows))
        constexpr float S0 = 0.15811388300841897f;
        float h[64];
        {
            const float4* rowts = reinterpret_cast<const float4*>(W0 + ts * 64);
            const float4* rowtd = reinterpret_cast<const float4*>(W0 + (16 + td) * 64);
#pragma unroll
            for (int q = 0; q < 16; q++) {
                float4 a = __ldg(rowts + q);
                float4 b = __ldg(rowtd + q);
                h[4 * q + 0] = a.x + b.x; h[4 * q + 1] = a.y + b.y;
                h[4 * q + 2] = a.z + b.z; h[4 * q + 3] = a.w + b.w;
            }
#pragma unroll
            for (int j = 0; j < 8; j++) {
                const float bj = eb[j];
                const float4* br = reinterpret_cast<const float4*>(bes + j * 64);
#pragma unroll
                for (int q = 0; q < 16; q++) {
                    float4 w = br[q];
                    h[4 * q + 0] = fmaf(bj, w.x, h[4 * q + 0]);
                    h[4 * q + 1] = fmaf(bj, w.y, h[4 * q + 1]);
                    h[4 * q + 2] = fmaf(bj, w.z, h[4 * q + 2]);
                    h[4 * q + 3] = fmaf(bj, w.w, h[4 * q + 3]);
                }
            }
        }

        // split h -> bf16 hi/lo; store pairs (stride 35 u32 per edge)
        uint32_t* hhw = reinterpret_cast<uint32_t*>(smc + OFF_HHI) + tid * 35;
        uint32_t* hlw = reinterpret_cast<uint32_t*>(smc + OFF_HLO) + tid * 35;
#pragma unroll
        for (int q = 0; q < 32; q++) {
            float v0 = silu_f(S0 * h[2 * q]);
            float v1 = silu_f(S0 * h[2 * q + 1]);
            __nv_bfloat16 h0 = __float2bfloat16(v0), h1 = __float2bfloat16(v1);
            float r0 = v0 - __bfloat162float(h0);
            float r1 = v1 - __bfloat162float(h1);
            __nv_bfloat16 l0 = __float2bfloat16(r0), l1 = __float2bfloat16(r1);
            hhw[q] = (uint32_t)__bfloat16_as_ushort(h0) | ((uint32_t)__bfloat16_as_ushort(h1) << 16);
            hlw[q] = (uint32_t)__bfloat16_as_ushort(l0) | ((uint32_t)__bfloat16_as_ushort(l1) << 16);
        }

        // tp scalars (cut + INV2 folded)
        constexpr float SQ3  = 1.7320508075688772f;
        constexpr float INV2 = 0.70710678118654752f;
        const float s = shv.x, vx = shv.y, vy = shv.z, vz = shv.w;
        const float tw0 = cst[8],  tw1 = cst[9],  tw2 = cst[10];
        const float tw3 = cst[11], tw4 = cst[12], tw5 = cst[13];
        const float tw6 = cst[14];
        const float sq   = s * s;
        const float dotv = (vx * vx + vy * vy + vz * vz) * (1.0f / SQ3);
        float* tp = tparr + tid * 16;
        tp[0] = cl;
        tp[1] = INV2 * (tw0 * sq + tw1 * dotv) * cl;
        tp[2] = INV2 * (tw4 * sq + tw5 * dotv) * cl;
        const float sa = INV2 * tw2 * s * cl;
        const float sb = INV2 * tw3 * s * cl;
        tp[3] = sa * vx; tp[4] = sa * vy; tp[5] = sa * vz;
        tp[6] = sb * vx; tp[7] = sb * vy; tp[8] = sb * vz;
        const float t6c = tw6 * cl;
        tp[9]  = t6c * SQ3 * vx * vy;
        tp[10] = t6c * SQ3 * vy * vz;
        tp[11] = t6c * (vz * vz - 0.5f * (vx * vx + vy * vy));
        tp[12] = t6c * SQ3 * vx * vz;
        tp[13] = t6c * (0.5f * SQ3) * (vx * vx - vy * vy);
    }
    __syncthreads();   // B (h) and tp are now read cross-warp

    // ================= GEMM: warp owns 2 m-tiles for all 256 edges =================
    const uint4* afh = reinterpret_cast<const uint4*>(g_afrag_hi);
    const uint4* afl = reinterpret_cast<const uint4*>(g_afrag_lo);
    const uint32_t* hh = reinterpret_cast<const uint32_t*>(smc + OFF_HHI);
    const uint32_t* hl = reinterpret_cast<const uint32_t*>(smc + OFF_HLO);
    float* bufbase = reinterpret_cast<float*>(smc + OFF_BUF) + warp * (2 * 8 * BSTR);

    const int mt0 = g_mt0[warp];
    const int mt1 = g_mt1[warp];

    // A fragments in registers — loaded ONCE per warp
    uint4 AH0[4], AH1[4], AL0[4], AL1[4];
#pragma unroll
    for (int kt = 0; kt < 4; kt++) {
        AH0[kt] = __ldg(afh + (mt0 * 4 + kt) * 32 + lane);
        AH1[kt] = __ldg(afh + (mt1 * 4 + kt) * 32 + lane);
        AL0[kt] = __ldg(afl + (mt0 * 4 + kt) * 32 + lane);
        AL1[kt] = __ldg(afl + (mt1 * 4 + kt) * 32 + lane);
    }

    int bufsel = 0;
#pragma unroll 1
    for (int ng = 0; ng < 32; ng++) {
        const int eb = (ng * 8 + g) * 35 + t3;
        float acc0[4] = {0.f, 0.f, 0.f, 0.f};
        float acc1[4] = {0.f, 0.f, 0.f, 0.f};
#pragma unroll
        for (int kt = 0; kt < 4; kt++) {
            const int ko = kt * 8;
            const uint32_t bha = hh[eb + ko], bhb = hh[eb + ko + 4];
            const uint32_t bla = hl[eb + ko], blb = hl[eb + ko + 4];
            mma16816(acc0, AH0[kt], bha, bhb);
            mma16816(acc1, AH1[kt], bha, bhb);
            mma16816(acc0, AH0[kt], bla, blb);
            mma16816(acc1, AH1[kt], bla, blb);
            mma16816(acc0, AL0[kt], bha, bhb);
            mma16816(acc1, AL1[kt], bha, bhb);
        }

        float* bwarp = bufbase + bufsel * (8 * BSTR);
        bufsel ^= 1;
        // scatter D frags: rows = edges (2*t3, 2*t3+1), cols = m within tile pair
        bwarp[(2 * t3)     * BSTR + g]          = acc0[0];
        bwarp[(2 * t3 + 1) * BSTR + g]          = acc0[1];
        bwarp[(2 * t3)     * BSTR + g + 8]      = acc0[2];
        bwarp[(2 * t3 + 1) * BSTR + g + 8]      = acc0[3];
        bwarp[(2 * t3)     * BSTR + 16 + g]     = acc1[0];
        bwarp[(2 * t3 + 1) * BSTR + 16 + g]     = acc1[1];
        bwarp[(2 * t3)     * BSTR + 16 + g + 8] = acc1[2];
        bwarp[(2 * t3 + 1) * BSTR + 16 + g + 8] = acc1[3];
        __syncwarp();

        const int el = ng * 8 + g;
        const size_t eg = (size_t)blockIdx.x * EPB + el;
        const float* tp   = tparr + el * 16;
        const float* row0 = bwarp + g * BSTR;
        float* lat_e  = lat_out  + eg * 128;
        float* feat_e = feat_out + eg * 288;
        epi_mtile(mt0, row0,      tp, lat_e, feat_e, t3);
        epi_mtile(mt1, row0 + 16, tp, lat_e, feat_e, t3);
    }
}

extern "C" void kernel_launch(void* const* d_in, const int* in_sizes, int n_in,
                              void* d_out, int out_size)
{
    const int*   eidx   = (const int*)  d_in[0];
    const float* esh    = (const float*)d_in[1];
    const float* elen   = (const float*)d_in[2];
    const float* onehot = (const float*)d_in[3];
    const float* bw     = (const float*)d_in[4];
    const float* tpw    = (const float*)d_in[5];
    const float* W0     = (const float*)d_in[6];
    const float* W1     = (const float*)d_in[7];
    const float* We     = (const float*)d_in[8];
    float* out = (float*)d_out;

    const int E = in_sizes[0] / 2;       // 524288
    const int blocks = E / EPB;          // 2048

    afrag_kernel<<<36, 256>>>(W1, We);

    cudaFuncSetAttribute(e3_mma_kernel,
                         cudaFuncAttributeMaxDynamicSharedMemorySize, SMEM_BYTES);
    e3_mma_kernel<<<blocks, TPB, SMEM_BYTES>>>(
        eidx, esh, elen, onehot, bw, tpw, W0, out, E);
}

// round 15
// speedup vs baseline: 1.1317x; 1.1317x over previous
#include <cuda_runtime.h>
#include <cuda_bf16.h>
#include <cstdint>

typedef unsigned long long u64;

// ---------------- config ----------------
constexpr int TPB = 288;        // 9 warps; warp owns 2 m-tiles for all 256 edges
constexpr int EPB = 256;

// smem byte offsets
constexpr int OFF_HHI = 0;               // h hi: 256 x 35 u32 = 35840B
constexpr int OFF_HLO = 35840;           // h lo: 35840B
constexpr int OFF_TP  = 71680;           // tp: 256 x 17 f32 = 17408B (stride 17: bank-clean)
constexpr int OFF_BUF = 89088;           // 9 warps x 2 bufs x 160 f32 = 11520B
constexpr int OFF_BES = 100608;          // bessel W0 rows: 512 f32 = 2048B
constexpr int OFF_CST = 102656;          // 16 f32
constexpr int SMEM_BYTES = 102720;       // x2 CTAs = 205,440B

constexpr int BSTR = 20;                 // buf row stride (floats): conflict-light
constexpr int TPS  = 17;                 // tp row stride (floats)

// warp -> m-tile pair. Slot A: warps 0-7 latent (direct STG), warp 8 tile 10 (buffered).
// Slot B: always buffered. mtiles: 0-7 latent, 8-11 f0, 12-15 f1, 16-17 f2.
__device__ const int g_mtA[9] = {0, 1, 2, 3, 4, 5, 6, 7, 10};
__device__ const int g_mtB[9] = {16, 17, 12, 13, 14, 15, 8, 9, 11};

// ---------------- device scratch ----------------
__device__ __align__(16) uint32_t g_afrag_hi[9216];
__device__ __align__(16) uint32_t g_afrag_lo[9216];

__device__ __forceinline__ float silu_f(float v) { return v / (1.0f + __expf(-v)); }

// ---------------- fused prep: A fragments (hi/lo bf16), W1@We inline ----------------
__global__ void afrag_kernel(const float* __restrict__ W1, const float* __restrict__ We) {
    constexpr float S1 = 1.6789f * 0.125f;
    constexpr float S2 = 0.08838834764831845f;
    int idx = blockIdx.x * blockDim.x + threadIdx.x;
    if (idx >= 9216) return;
    int ri = idx & 3, t = (idx >> 2) & 31, kt = (idx >> 7) & 3, mt = idx >> 9;
    int m  = mt * 16 + (t >> 2) + (ri & 1) * 8;
    int k0 = kt * 16 + (t & 3) * 2 + (ri >> 1) * 8;

    float v0, v1;
    if (m < 128) {
        v0 = W1[k0 * 128 + m] * S1;
        v1 = W1[(k0 + 1) * 128 + m] * S1;
    } else {
        int cm;
        if (m < 192)      { int p = (m - 128) >> 1, s = (m - 128) & 1; cm = p + 32 * s; }
        else if (m < 256) { int p = (m - 192) >> 1, s = (m - 192) & 1; cm = 64 + p + 32 * s; }
        else                cm = 128 + (m - 256);
        float a0 = 0.0f, a1 = 0.0f;
        const float* w1a = W1 + k0 * 128;
        const float* w1b = W1 + (k0 + 1) * 128;
#pragma unroll 8
        for (int j = 0; j < 128; j++) {
            const float we = __ldg(We + j * 160 + cm);
            a0 = fmaf(__ldg(w1a + j), we, a0);
            a1 = fmaf(__ldg(w1b + j), we, a1);
        }
        v0 = a0 * (S1 * S2);
        v1 = a1 * (S1 * S2);
    }

    __nv_bfloat16 h0 = __float2bfloat16(v0);
    __nv_bfloat16 h1 = __float2bfloat16(v1);
    __nv_bfloat16 l0 = __float2bfloat16(v0 - __bfloat162float(h0));
    __nv_bfloat16 l1 = __float2bfloat16(v1 - __bfloat162float(h1));
    g_afrag_hi[idx] = (uint32_t)__bfloat16_as_ushort(h0) | ((uint32_t)__bfloat16_as_ushort(h1) << 16);
    g_afrag_lo[idx] = (uint32_t)__bfloat16_as_ushort(l0) | ((uint32_t)__bfloat16_as_ushort(l1) << 16);
}

// ---------------- mma helper ----------------
__device__ __forceinline__ void mma16816(float* d, const uint4& a, uint32_t b0, uint32_t b1) {
    asm volatile(
        "mma.sync.aligned.m16n8k16.row.col.f32.bf16.bf16.f32 "
        "{%0,%1,%2,%3}, {%4,%5,%6,%7}, {%8,%9}, {%0,%1,%2,%3};"
        : "+f"(d[0]), "+f"(d[1]), "+f"(d[2]), "+f"(d[3])
        : "r"(a.x), "r"(a.y), "r"(a.z), "r"(a.w), "r"(b0), "r"(b1));
}

// ---------------- buffered epilogue for one 16-col m-tile (mt >= 8) ----------------
// buf rows = 8 edges (stride BSTR), cols = 16 m values. edge = ng*8 + g.
__device__ __forceinline__ void epi_buf(int mt, const float* __restrict__ row,
                                        const float* __restrict__ tp,
                                        float* __restrict__ feat_e, int t3) {
    if (mt < 12) {
        const float ta = tp[1], tb = tp[2];
        float2 v;
        v.x = row[4 * t3]     * ta + row[4 * t3 + 1] * tb;
        v.y = row[4 * t3 + 2] * ta + row[4 * t3 + 3] * tb;
        *reinterpret_cast<float2*>(feat_e + (mt - 8) * 8 + 2 * t3) = v;
    } else if (mt < 16) {
        float* dst = feat_e + 32 + (mt - 12) * 24 + 6 * t3;
        const float a0 = row[4 * t3], b0 = row[4 * t3 + 1];
        const float a1 = row[4 * t3 + 2], b1 = row[4 * t3 + 3];
        float2 v0, v1, v2;
        v0.x = a0 * tp[3] + b0 * tp[6];
        v0.y = a0 * tp[4] + b0 * tp[7];
        v1.x = a0 * tp[5] + b0 * tp[8];
        v1.y = a1 * tp[3] + b1 * tp[6];
        v2.x = a1 * tp[4] + b1 * tp[7];
        v2.y = a1 * tp[5] + b1 * tp[8];
        reinterpret_cast<float2*>(dst)[0] = v0;
        reinterpret_cast<float2*>(dst)[1] = v1;
        reinterpret_cast<float2*>(dst)[2] = v2;
    } else {
        float* dst = feat_e + 128 + (mt - 16) * 80 + 20 * t3;
        float v[20];
#pragma unroll
        for (int j = 0; j < 4; j++) {
            const float a = row[4 * t3 + j];
#pragma unroll
            for (int i = 0; i < 5; i++) v[5 * j + i] = a * tp[9 + i];
        }
#pragma unroll
        for (int t = 0; t < 5; t++)
            reinterpret_cast<float4*>(dst)[t] =
                make_float4(v[4 * t], v[4 * t + 1], v[4 * t + 2], v[4 * t + 3]);
    }
}

// ---------------- main kernel ----------------
__global__ void __launch_bounds__(TPB, 2)
e3_mma_kernel(const int*   __restrict__ eidx,
              const float* __restrict__ esh,
              const float* __restrict__ elen,
              const float* __restrict__ onehot,
              const float* __restrict__ bw,
              const float* __restrict__ tpw,
              const float* __restrict__ W0,
              float*       __restrict__ out,
              int E)
{
    extern __shared__ __align__(16) char smc[];
    const int tid  = threadIdx.x;
    const int warp = tid >> 5;
    const int lane = tid & 31;
    const int t3   = lane & 3;
    const int g    = lane >> 2;

    // ---- small cooperative loads ----
    if (tid < 256) {
        float* bes = reinterpret_cast<float*>(smc + OFF_BES);
        bes[tid]       = W0[32 * 64 + tid];
        bes[tid + 256] = W0[32 * 64 + 256 + tid];
        float* cst = reinterpret_cast<float*>(smc + OFF_CST);
        if (tid < 8)       cst[tid] = bw[tid];
        else if (tid < 15) cst[tid] = tpw[tid - 8];
    }
    __syncthreads();

    const float* bes = reinterpret_cast<const float*>(smc + OFF_BES);
    const float* cst = reinterpret_cast<const float*>(smc + OFF_CST);
    float* tparr = reinterpret_cast<float*>(smc + OFF_TP);

    float* __restrict__ lat_out  = out;
    float* __restrict__ feat_out = out + (size_t)E * 128;
    float* __restrict__ cut_out  = out + (size_t)E * 416;

    // ================= stage 1: first 256 threads, one edge each =================
    if (tid < 256) {
        const int e = blockIdx.x * EPB + tid;
        const int   src = eidx[e];
        const int   dst = eidx[E + e];
        const float r   = elen[e];
        const float4 shv = reinterpret_cast<const float4*>(esh)[e];

        int ts = 0, td = 0;
        {
            const float4* rs = reinterpret_cast<const float4*>(onehot + (size_t)src * 16);
            const float4* rd = reinterpret_cast<const float4*>(onehot + (size_t)dst * 16);
#pragma unroll
            for (int q4 = 0; q4 < 4; q4++) {
                float4 a = __ldg(rs + q4); float4 b = __ldg(rd + q4);
                int base = q4 * 4;
                if (a.x > 0.5f) ts = base;     if (a.y > 0.5f) ts = base + 1;
                if (a.z > 0.5f) ts = base + 2; if (a.w > 0.5f) ts = base + 3;
                if (b.x > 0.5f) td = base;     if (b.y > 0.5f) td = base + 1;
                if (b.z > 0.5f) td = base + 2; if (b.w > 0.5f) td = base + 3;
            }
        }

        const float x    = r * 0.2f;
        const float invr = 1.0f / r;
        float eb[8];
#pragma unroll
        for (int j = 0; j < 8; j++)
            eb[j] = 0.4f * __sinf(cst[j] * x) * invr;

        const float x3 = x * x * x, x6 = x3 * x3, x7 = x6 * x, x8 = x7 * x;
        const float poly = 1.0f - 28.0f * x6 + 48.0f * x7 - 21.0f * x8;
        const float cutv = (x < 1.0f) ? poly : 0.0f;
        const float cl   = (cutv > 0.0f) ? cutv : 0.0f;
        cut_out[e] = cutv;

        constexpr float S0 = 0.15811388300841897f;
        float h[64];
        {
            const float4* rowts = reinterpret_cast<const float4*>(W0 + ts * 64);
            const float4* rowtd = reinterpret_cast<const float4*>(W0 + (16 + td) * 64);
#pragma unroll
            for (int q = 0; q < 16; q++) {
                float4 a = __ldg(rowts + q);
                float4 b = __ldg(rowtd + q);
                h[4 * q + 0] = a.x + b.x; h[4 * q + 1] = a.y + b.y;
                h[4 * q + 2] = a.z + b.z; h[4 * q + 3] = a.w + b.w;
            }
#pragma unroll
            for (int j = 0; j < 8; j++) {
                const float bj = eb[j];
                const float4* br = reinterpret_cast<const float4*>(bes + j * 64);
#pragma unroll
                for (int q = 0; q < 16; q++) {
                    float4 w = br[q];
                    h[4 * q + 0] = fmaf(bj, w.x, h[4 * q + 0]);
                    h[4 * q + 1] = fmaf(bj, w.y, h[4 * q + 1]);
                    h[4 * q + 2] = fmaf(bj, w.z, h[4 * q + 2]);
                    h[4 * q + 3] = fmaf(bj, w.w, h[4 * q + 3]);
                }
            }
        }

        // split h -> bf16 hi/lo; store pairs (stride 35 u32 per edge)
        uint32_t* hhw = reinterpret_cast<uint32_t*>(smc + OFF_HHI) + tid * 35;
        uint32_t* hlw = reinterpret_cast<uint32_t*>(smc + OFF_HLO) + tid * 35;
#pragma unroll
        for (int q = 0; q < 32; q++) {
            float v0 = silu_f(S0 * h[2 * q]);
            float v1 = silu_f(S0 * h[2 * q + 1]);
            __nv_bfloat16 h0 = __float2bfloat16(v0), h1 = __float2bfloat16(v1);
            float r0 = v0 - __bfloat162float(h0);
            float r1 = v1 - __bfloat162float(h1);
            __nv_bfloat16 l0 = __float2bfloat16(r0), l1 = __float2bfloat16(r1);
            hhw[q] = (uint32_t)__bfloat16_as_ushort(h0) | ((uint32_t)__bfloat16_as_ushort(h1) << 16);
            hlw[q] = (uint32_t)__bfloat16_as_ushort(l0) | ((uint32_t)__bfloat16_as_ushort(l1) << 16);
        }

        // tp scalars (cut + INV2 folded), stride 17
        constexpr float SQ3  = 1.7320508075688772f;
        constexpr float INV2 = 0.70710678118654752f;
        const float s = shv.x, vx = shv.y, vy = shv.z, vz = shv.w;
        const float tw0 = cst[8],  tw1 = cst[9],  tw2 = cst[10];
        const float tw3 = cst[11], tw4 = cst[12], tw5 = cst[13];
        const float tw6 = cst[14];
        const float sq   = s * s;
        const float dotv = (vx * vx + vy * vy + vz * vz) * (1.0f / SQ3);
        float* tp = tparr + tid * TPS;
        tp[0] = cl;
        tp[1] = INV2 * (tw0 * sq + tw1 * dotv) * cl;
        tp[2] = INV2 * (tw4 * sq + tw5 * dotv) * cl;
        const float sa = INV2 * tw2 * s * cl;
        const float sb = INV2 * tw3 * s * cl;
        tp[3] = sa * vx; tp[4] = sa * vy; tp[5] = sa * vz;
        tp[6] = sb * vx; tp[7] = sb * vy; tp[8] = sb * vz;
        const float t6c = tw6 * cl;
        tp[9]  = t6c * SQ3 * vx * vy;
        tp[10] = t6c * SQ3 * vy * vz;
        tp[11] = t6c * (vz * vz - 0.5f * (vx * vx + vy * vy));
        tp[12] = t6c * SQ3 * vx * vz;
        tp[13] = t6c * (0.5f * SQ3) * (vx * vx - vy * vy);
    }
    __syncthreads();

    // ================= GEMM: warp owns 2 m-tiles for all 256 edges =================
    const uint4* afh = reinterpret_cast<const uint4*>(g_afrag_hi);
    const uint4* afl = reinterpret_cast<const uint4*>(g_afrag_lo);
    const uint32_t* hh = reinterpret_cast<const uint32_t*>(smc + OFF_HHI);
    const uint32_t* hl = reinterpret_cast<const uint32_t*>(smc + OFF_HLO);
    float* buf0 = reinterpret_cast<float*>(smc + OFF_BUF) + warp * (2 * 8 * BSTR);
    float* buf1 = buf0 + 8 * BSTR;

    const int mtA = g_mtA[warp];
    const int mtB = g_mtB[warp];
    const bool directA = (mtA < 8);

    uint4 AH0[4], AH1[4], AL0[4], AL1[4];
#pragma unroll
    for (int kt = 0; kt < 4; kt++) {
        AH0[kt] = __ldg(afh + (mtA * 4 + kt) * 32 + lane);
        AH1[kt] = __ldg(afh + (mtB * 4 + kt) * 32 + lane);
        AL0[kt] = __ldg(afl + (mtA * 4 + kt) * 32 + lane);
        AL1[kt] = __ldg(afl + (mtB * 4 + kt) * 32 + lane);
    }

#pragma unroll 1
    for (int ng = 0; ng < 32; ng++) {
        const int eb = (ng * 8 + g) * 35 + t3;
        float acc0[4] = {0.f, 0.f, 0.f, 0.f};
        float acc1[4] = {0.f, 0.f, 0.f, 0.f};
#pragma unroll
        for (int kt = 0; kt < 4; kt++) {
            const int ko = kt * 8;
            const uint32_t bha = hh[eb + ko], bhb = hh[eb + ko + 4];
            const uint32_t bla = hl[eb + ko], blb = hl[eb + ko + 4];
            mma16816(acc0, AH0[kt], bha, bhb);
            mma16816(acc1, AH1[kt], bha, bhb);
            mma16816(acc0, AH0[kt], bla, blb);
            mma16816(acc1, AH1[kt], bla, blb);
            mma16816(acc0, AL0[kt], bha, bhb);
            mma16816(acc1, AL1[kt], bha, bhb);
        }

        // ---- slot A: direct-STG latent (sector-aligned) or scatter to buf0 ----
        if (directA) {
            const int el0 = ng * 8 + 2 * t3;      // D-frag col mapping: edges 2t3, 2t3+1
            const int el1 = el0 + 1;
            const float cl0 = tparr[el0 * TPS];
            const float cl1 = tparr[el1 * TPS];
            const size_t eg0 = (size_t)blockIdx.x * EPB + el0;
            const size_t eg1 = eg0 + 1;
            lat_out[eg0 * 128 + mtA * 16 + g]     = acc0[0] * cl0;
            lat_out[eg1 * 128 + mtA * 16 + g]     = acc0[1] * cl1;
            lat_out[eg0 * 128 + mtA * 16 + g + 8] = acc0[2] * cl0;
            lat_out[eg1 * 128 + mtA * 16 + g + 8] = acc0[3] * cl1;
        } else {
            buf0[(2 * t3)     * BSTR + g]     = acc0[0];
            buf0[(2 * t3 + 1) * BSTR + g]     = acc0[1];
            buf0[(2 * t3)     * BSTR + g + 8] = acc0[2];
            buf0[(2 * t3 + 1) * BSTR + g + 8] = acc0[3];
        }

        // ---- slot B: scatter to buf1 ----
        buf1[(2 * t3)     * BSTR + g]     = acc1[0];
        buf1[(2 * t3 + 1) * BSTR + g]     = acc1[1];
        buf1[(2 * t3)     * BSTR + g + 8] = acc1[2];
        buf1[(2 * t3 + 1) * BSTR + g + 8] = acc1[3];
        __syncwarp();

        // ---- buffered epilogues: edge = ng*8 + g ----
        const int el = ng * 8 + g;
        const size_t eg = (size_t)blockIdx.x * EPB + el;
        const float* tp = tparr + el * TPS;
        float* feat_e = feat_out + eg * 288;
        if (!directA) epi_buf(mtA, buf0 + g * BSTR, tp, feat_e, t3);
        epi_buf(mtB, buf1 + g * BSTR, tp, feat_e, t3);
        __syncwarp();
    }
}

extern "C" void kernel_launch(void* const* d_in, const int* in_sizes, int n_in,
                              void* d_out, int out_size)
{
    const int*   eidx   = (const int*)  d_in[0];
    const float* esh    = (const float*)d_in[1];
    const float* elen   = (const float*)d_in[2];
    const float* onehot = (const float*)d_in[3];
    const float* bw     = (const float*)d_in[4];
    const float* tpw    = (const float*)d_in[5];
    const float* W0     = (const float*)d_in[6];
    const float* W1     = (const float*)d_in[7];
    const float* We     = (const float*)d_in[8];
    float* out = (float*)d_out;

    const int E = in_sizes[0] / 2;       // 524288
    const int blocks = E / EPB;          // 2048

    afrag_kernel<<<36, 256>>>(W1, We);

    cudaFuncSetAttribute(e3_mma_kernel,
                         cudaFuncAttributeMaxDynamicSharedMemorySize, SMEM_BYTES);
    e3_mma_kernel<<<blocks, TPB, SMEM_BYTES>>>(
        eidx, esh, elen, onehot, bw, tpw, W0, out, E);
}

// round 16
// speedup vs baseline: 1.3235x; 1.1695x over previous
#include <cuda_runtime.h>
#include <cuda_fp16.h>
#include <cstdint>

typedef unsigned long long u64;

// ---------------- config ----------------
constexpr int TPB = 288;        // 9 warps; warp owns 2 m-tiles for all 256 edges
constexpr int EPB = 256;

// smem byte offsets
constexpr int OFF_HHI = 0;               // h fp16, paired layout: 256 x 40 u32 = 40960B
constexpr int OFF_TP  = 40960;           // tp: 256 x 17 f32 = 17408B
constexpr int OFF_BUF = 58368;           // 9 warps x 2 bufs x 160 f32 = 11520B
constexpr int OFF_BES = 69888;           // bessel W0 rows: 512 f32 = 2048B
constexpr int OFF_CST = 71936;           // 16 f32
constexpr int SMEM_BYTES = 72000;        // x2 CTAs = 144,000B

constexpr int BSTR = 20;                 // buf row stride (floats)
constexpr int TPS  = 17;                 // tp row stride (floats)
constexpr int HSTR = 40;                 // h row stride (u32): LDS.64 conflict-free

// warp -> m-tile pair. Slot A: warps 0-7 latent (direct STG), warp 8 tile 10.
__device__ const int g_mtA[9] = {0, 1, 2, 3, 4, 5, 6, 7, 10};
__device__ const int g_mtB[9] = {16, 17, 12, 13, 14, 15, 8, 9, 11};

// ---------------- device scratch ----------------
__device__ __align__(16) uint32_t g_afrag_hi[9216];   // fp16 pairs
__device__ __align__(16) uint32_t g_afrag_lo[9216];

__device__ __forceinline__ float silu_f(float v) { return v / (1.0f + __expf(-v)); }
__device__ __forceinline__ uint32_t pkh(float a, float b) {
    __half2 h = __floats2half2_rn(a, b);
    return *reinterpret_cast<uint32_t*>(&h);
}

// ---------------- fused prep: A fragments (hi/lo fp16), W1@We inline ----------------
__global__ void afrag_kernel(const float* __restrict__ W1, const float* __restrict__ We) {
    constexpr float S1 = 1.6789f * 0.125f;
    constexpr float S2 = 0.08838834764831845f;
    int idx = blockIdx.x * blockDim.x + threadIdx.x;
    if (idx >= 9216) return;
    int ri = idx & 3, t = (idx >> 2) & 31, kt = (idx >> 7) & 3, mt = idx >> 9;
    int m  = mt * 16 + (t >> 2) + (ri & 1) * 8;
    int k0 = kt * 16 + (t & 3) * 2 + (ri >> 1) * 8;

    float v0, v1;
    if (m < 128) {
        v0 = W1[k0 * 128 + m] * S1;
        v1 = W1[(k0 + 1) * 128 + m] * S1;
    } else {
        int cm;
        if (m < 192)      { int p = (m - 128) >> 1, s = (m - 128) & 1; cm = p + 32 * s; }
        else if (m < 256) { int p = (m - 192) >> 1, s = (m - 192) & 1; cm = 64 + p + 32 * s; }
        else                cm = 128 + (m - 256);
        float a0 = 0.0f, a1 = 0.0f;
        const float* w1a = W1 + k0 * 128;
        const float* w1b = W1 + (k0 + 1) * 128;
#pragma unroll 8
        for (int j = 0; j < 128; j++) {
            const float we = __ldg(We + j * 160 + cm);
            a0 = fmaf(__ldg(w1a + j), we, a0);
            a1 = fmaf(__ldg(w1b + j), we, a1);
        }
        v0 = a0 * (S1 * S2);
        v1 = a1 * (S1 * S2);
    }

    __half h0 = __float2half_rn(v0);
    __half h1 = __float2half_rn(v1);
    float r0 = v0 - __half2float(h0);
    float r1 = v1 - __half2float(h1);
    g_afrag_hi[idx] = (uint32_t)__half_as_ushort(h0) | ((uint32_t)__half_as_ushort(h1) << 16);
    g_afrag_lo[idx] = (uint32_t)__half_as_ushort(__float2half_rn(r0)) |
                      ((uint32_t)__half_as_ushort(__float2half_rn(r1)) << 16);
}

// ---------------- mma helper (fp16 in, fp32 acc) ----------------
__device__ __forceinline__ void mma16816(float* d, const uint4& a, uint32_t b0, uint32_t b1) {
    asm volatile(
        "mma.sync.aligned.m16n8k16.row.col.f32.f16.f16.f32 "
        "{%0,%1,%2,%3}, {%4,%5,%6,%7}, {%8,%9}, {%0,%1,%2,%3};"
        : "+f"(d[0]), "+f"(d[1]), "+f"(d[2]), "+f"(d[3])
        : "r"(a.x), "r"(a.y), "r"(a.z), "r"(a.w), "r"(b0), "r"(b1));
}

// ---------------- buffered epilogue for one 16-col m-tile (mt >= 8) ----------------
__device__ __forceinline__ void epi_buf(int mt, const float* __restrict__ row,
                                        const float* __restrict__ tp,
                                        float* __restrict__ feat_e, int t3) {
    if (mt < 12) {
        const float ta = tp[1], tb = tp[2];
        float2 v;
        v.x = row[4 * t3]     * ta + row[4 * t3 + 1] * tb;
        v.y = row[4 * t3 + 2] * ta + row[4 * t3 + 3] * tb;
        *reinterpret_cast<float2*>(feat_e + (mt - 8) * 8 + 2 * t3) = v;
    } else if (mt < 16) {
        float* dst = feat_e + 32 + (mt - 12) * 24 + 6 * t3;
        const float a0 = row[4 * t3], b0 = row[4 * t3 + 1];
        const float a1 = row[4 * t3 + 2], b1 = row[4 * t3 + 3];
        float2 v0, v1, v2;
        v0.x = a0 * tp[3] + b0 * tp[6];
        v0.y = a0 * tp[4] + b0 * tp[7];
        v1.x = a0 * tp[5] + b0 * tp[8];
        v1.y = a1 * tp[3] + b1 * tp[6];
        v2.x = a1 * tp[4] + b1 * tp[7];
        v2.y = a1 * tp[5] + b1 * tp[8];
        reinterpret_cast<float2*>(dst)[0] = v0;
        reinterpret_cast<float2*>(dst)[1] = v1;
        reinterpret_cast<float2*>(dst)[2] = v2;
    } else {
        float* dst = feat_e + 128 + (mt - 16) * 80 + 20 * t3;
        float v[20];
#pragma unroll
        for (int j = 0; j < 4; j++) {
            const float a = row[4 * t3 + j];
#pragma unroll
            for (int i = 0; i < 5; i++) v[5 * j + i] = a * tp[9 + i];
        }
#pragma unroll
        for (int t = 0; t < 5; t++)
            reinterpret_cast<float4*>(dst)[t] =
                make_float4(v[4 * t], v[4 * t + 1], v[4 * t + 2], v[4 * t + 3]);
    }
}

// ---------------- main kernel ----------------
__global__ void __launch_bounds__(TPB, 2)
e3_mma_kernel(const int*   __restrict__ eidx,
              const float* __restrict__ esh,
              const float* __restrict__ elen,
              const float* __restrict__ onehot,
              const float* __restrict__ bw,
              const float* __restrict__ tpw,
              const float* __restrict__ W0,
              float*       __restrict__ out,
              int E)
{
    extern __shared__ __align__(16) char smc[];
    const int tid  = threadIdx.x;
    const int warp = tid >> 5;
    const int lane = tid & 31;
    const int t3   = lane & 3;
    const int g    = lane >> 2;

    // ---- small cooperative loads ----
    if (tid < 256) {
        float* bes = reinterpret_cast<float*>(smc + OFF_BES);
        bes[tid]       = W0[32 * 64 + tid];
        bes[tid + 256] = W0[32 * 64 + 256 + tid];
        float* cst = reinterpret_cast<float*>(smc + OFF_CST);
        if (tid < 8)       cst[tid] = bw[tid];
        else if (tid < 15) cst[tid] = tpw[tid - 8];
    }
    __syncthreads();

    const float* bes = reinterpret_cast<const float*>(smc + OFF_BES);
    const float* cst = reinterpret_cast<const float*>(smc + OFF_CST);
    float* tparr = reinterpret_cast<float*>(smc + OFF_TP);

    float* __restrict__ lat_out  = out;
    float* __restrict__ feat_out = out + (size_t)E * 128;
    float* __restrict__ cut_out  = out + (size_t)E * 416;

    // ================= stage 1: first 256 threads, one edge each =================
    if (tid < 256) {
        const int e = blockIdx.x * EPB + tid;
        const int   src = eidx[e];
        const int   dst = eidx[E + e];
        const float r   = elen[e];
        const float4 shv = reinterpret_cast<const float4*>(esh)[e];

        int ts = 0, td = 0;
        {
            const float4* rs = reinterpret_cast<const float4*>(onehot + (size_t)src * 16);
            const float4* rd = reinterpret_cast<const float4*>(onehot + (size_t)dst * 16);
#pragma unroll
            for (int q4 = 0; q4 < 4; q4++) {
                float4 a = __ldg(rs + q4); float4 b = __ldg(rd + q4);
                int base = q4 * 4;
                if (a.x > 0.5f) ts = base;     if (a.y > 0.5f) ts = base + 1;
                if (a.z > 0.5f) ts = base + 2; if (a.w > 0.5f) ts = base + 3;
                if (b.x > 0.5f) td = base;     if (b.y > 0.5f) td = base + 1;
                if (b.z > 0.5f) td = base + 2; if (b.w > 0.5f) td = base + 3;
            }
        }

        const float x    = r * 0.2f;
        const float invr = 1.0f / r;
        float eb[8];
#pragma unroll
        for (int j = 0; j < 8; j++)
            eb[j] = 0.4f * __sinf(cst[j] * x) * invr;

        const float x3 = x * x * x, x6 = x3 * x3, x7 = x6 * x, x8 = x7 * x;
        const float poly = 1.0f - 28.0f * x6 + 48.0f * x7 - 21.0f * x8;
        const float cutv = (x < 1.0f) ? poly : 0.0f;
        const float cl   = (cutv > 0.0f) ? cutv : 0.0f;
        cut_out[e] = cutv;

        constexpr float S0 = 0.15811388300841897f;
        float h[64];
        {
            const float4* rowts = reinterpret_cast<const float4*>(W0 + ts * 64);
            const float4* rowtd = reinterpret_cast<const float4*>(W0 + (16 + td) * 64);
#pragma unroll
            for (int q = 0; q < 16; q++) {
                float4 a = __ldg(rowts + q);
                float4 b = __ldg(rowtd + q);
                h[4 * q + 0] = a.x + b.x; h[4 * q + 1] = a.y + b.y;
                h[4 * q + 2] = a.z + b.z; h[4 * q + 3] = a.w + b.w;
            }
#pragma unroll
            for (int j = 0; j < 8; j++) {
                const float bj = eb[j];
                const float4* br = reinterpret_cast<const float4*>(bes + j * 64);
#pragma unroll
                for (int q = 0; q < 16; q++) {
                    float4 w = br[q];
                    h[4 * q + 0] = fmaf(bj, w.x, h[4 * q + 0]);
                    h[4 * q + 1] = fmaf(bj, w.y, h[4 * q + 1]);
                    h[4 * q + 2] = fmaf(bj, w.z, h[4 * q + 2]);
                    h[4 * q + 3] = fmaf(bj, w.w, h[4 * q + 3]);
                }
            }
#pragma unroll
            for (int k = 0; k < 64; k++) h[k] = silu_f(S0 * h[k]);
        }

        // store h as fp16 pairs in (b0,b1)-paired layout:
        // old u32 q = 8*kt + rr (rr<4: b0 slot t3=rr; rr>=4: b1 slot t3=rr-4)
        // new pos = 8*kt + 2*(rr%4) + (rr>=4)
        uint32_t* hhw = reinterpret_cast<uint32_t*>(smc + OFF_HHI) + tid * HSTR;
#pragma unroll
        for (int q = 0; q < 32; q++) {
            const int kt = q >> 3, rr = q & 7;
            const int pos = 8 * kt + 2 * (rr & 3) + (rr >> 2);
            hhw[pos] = pkh(h[2 * q], h[2 * q + 1]);
        }

        // tp scalars (cut + INV2 folded), stride 17
        constexpr float SQ3  = 1.7320508075688772f;
        constexpr float INV2 = 0.70710678118654752f;
        const float s = shv.x, vx = shv.y, vy = shv.z, vz = shv.w;
        const float tw0 = cst[8],  tw1 = cst[9],  tw2 = cst[10];
        const float tw3 = cst[11], tw4 = cst[12], tw5 = cst[13];
        const float tw6 = cst[14];
        const float sq   = s * s;
        const float dotv = (vx * vx + vy * vy + vz * vz) * (1.0f / SQ3);
        float* tp = tparr + tid * TPS;
        tp[0] = cl;
        tp[1] = INV2 * (tw0 * sq + tw1 * dotv) * cl;
        tp[2] = INV2 * (tw4 * sq + tw5 * dotv) * cl;
        const float sa = INV2 * tw2 * s * cl;
        const float sb = INV2 * tw3 * s * cl;
        tp[3] = sa * vx; tp[4] = sa * vy; tp[5] = sa * vz;
        tp[6] = sb * vx; tp[7] = sb * vy; tp[8] = sb * vz;
        const float t6c = tw6 * cl;
        tp[9]  = t6c * SQ3 * vx * vy;
        tp[10] = t6c * SQ3 * vy * vz;
        tp[11] = t6c * (vz * vz - 0.5f * (vx * vx + vy * vy));
        tp[12] = t6c * SQ3 * vx * vz;
        tp[13] = t6c * (0.5f * SQ3) * (vx * vx - vy * vy);
    }
    __syncthreads();

    // ================= GEMM: warp owns 2 m-tiles for all 256 edges =================
    const uint4* afh = reinterpret_cast<const uint4*>(g_afrag_hi);
    const uint4* afl = reinterpret_cast<const uint4*>(g_afrag_lo);
    const u64* hh64 = reinterpret_cast<const u64*>(smc + OFF_HHI);
    float* buf0 = reinterpret_cast<float*>(smc + OFF_BUF) + warp * (2 * 8 * BSTR);
    float* buf1 = buf0 + 8 * BSTR;

    const int mtA = g_mtA[warp];
    const int mtB = g_mtB[warp];
    const bool directA = (mtA < 8);

    uint4 AH0[4], AH1[4], AL0[4], AL1[4];
#pragma unroll
    for (int kt = 0; kt < 4; kt++) {
        AH0[kt] = __ldg(afh + (mtA * 4 + kt) * 32 + lane);
        AH1[kt] = __ldg(afh + (mtB * 4 + kt) * 32 + lane);
        AL0[kt] = __ldg(afl + (mtA * 4 + kt) * 32 + lane);
        AL1[kt] = __ldg(afl + (mtB * 4 + kt) * 32 + lane);
    }

#pragma unroll 1
    for (int ng = 0; ng < 32; ng++) {
        const int eb = (ng * 8 + g) * (HSTR / 2) + t3;   // u64 index
        float acc0[4] = {0.f, 0.f, 0.f, 0.f};
        float acc1[4] = {0.f, 0.f, 0.f, 0.f};
#pragma unroll
        for (int kt = 0; kt < 4; kt++) {
            const u64 bv = hh64[eb + kt * 4];
            const uint32_t b0 = (uint32_t)bv;
            const uint32_t b1 = (uint32_t)(bv >> 32);
            mma16816(acc0, AH0[kt], b0, b1);
            mma16816(acc1, AH1[kt], b0, b1);
            mma16816(acc0, AL0[kt], b0, b1);
            mma16816(acc1, AL1[kt], b0, b1);
        }

        // ---- slot A: direct-STG latent or scatter to buf0 ----
        if (directA) {
            const int el0 = ng * 8 + 2 * t3;
            const int el1 = el0 + 1;
            const float cl0 = tparr[el0 * TPS];
            const float cl1 = tparr[el1 * TPS];
            const size_t eg0 = (size_t)blockIdx.x * EPB + el0;
            const size_t eg1 = eg0 + 1;
            lat_out[eg0 * 128 + mtA * 16 + g]     = acc0[0] * cl0;
            lat_out[eg1 * 128 + mtA * 16 + g]     = acc0[1] * cl1;
            lat_out[eg0 * 128 + mtA * 16 + g + 8] = acc0[2] * cl0;
            lat_out[eg1 * 128 + mtA * 16 + g + 8] = acc0[3] * cl1;
        } else {
            buf0[(2 * t3)     * BSTR + g]     = acc0[0];
            buf0[(2 * t3 + 1) * BSTR + g]     = acc0[1];
            buf0[(2 * t3)     * BSTR + g + 8] = acc0[2];
            buf0[(2 * t3 + 1) * BSTR + g + 8] = acc0[3];
        }

        // ---- slot B: scatter to buf1 ----
        buf1[(2 * t3)     * BSTR + g]     = acc1[0];
        buf1[(2 * t3 + 1) * BSTR + g]     = acc1[1];
        buf1[(2 * t3)     * BSTR + g + 8] = acc1[2];
        buf1[(2 * t3 + 1) * BSTR + g + 8] = acc1[3];
        __syncwarp();

        const int el = ng * 8 + g;
        const size_t eg = (size_t)blockIdx.x * EPB + el;
        const float* tp = tparr + el * TPS;
        float* feat_e = feat_out + eg * 288;
        if (!directA) epi_buf(mtA, buf0 + g * BSTR, tp, feat_e, t3);
        epi_buf(mtB, buf1 + g * BSTR, tp, feat_e, t3);
        __syncwarp();
    }
}

extern "C" void kernel_launch(void* const* d_in, const int* in_sizes, int n_in,
                              void* d_out, int out_size)
{
    const int*   eidx   = (const int*)  d_in[0];
    const float* esh    = (const float*)d_in[1];
    const float* elen   = (const float*)d_in[2];
    const float* onehot = (const float*)d_in[3];
    const float* bw     = (const float*)d_in[4];
    const float* tpw    = (const float*)d_in[5];
    const float* W0     = (const float*)d_in[6];
    const float* W1     = (const float*)d_in[7];
    const float* We     = (const float*)d_in[8];
    float* out = (float*)d_out;

    const int E = in_sizes[0] / 2;       // 524288
    const int blocks = E / EPB;          // 2048

    afrag_kernel<<<36, 256>>>(W1, We);

    cudaFuncSetAttribute(e3_mma_kernel,
                         cudaFuncAttributeMaxDynamicSharedMemorySize, SMEM_BYTES);
    e3_mma_kernel<<<blocks, TPB, SMEM_BYTES>>>(
        eidx, esh, elen, onehot, bw, tpw, W0, out, E);
}